// round 16
// baseline (speedup 1.0000x reference)
#include <cuda_runtime.h>
#include <cstdint>

// B=256, T_MAX=D_MAX=256, TP=DP=257
#define NTHREADS 512
#define L_PAD    66049          // 257*257
#define EPS_C    1e-12f
#define CUT_COST 30000          // cost=(nt+1)*(nd+1) above this -> cooperative 2-CTA

// Shared layout (floats)
#define U_OFF    0              // u local rows [260]; slot 259 = u_top
#define V_OFF    260            // v[260] (full, replicated in coop)
#define RMAX_OFF 520            // row max [260] (cost[] during remap)
#define RHAS_OFF 780            // row-has-assignment flags [260]
#define CMAX_OFF 1040           // col max [260]
#define SUP_OFF  1300           // per-warp sum(u) partials [16]
#define SVP_OFF  1316           // per-warp sum(v) partials [16]
#define SCR_OFF  1332           // half-split combine scratch [256]
#define SCR2_OFF 1588           // coop exchange buffer zrecv[264] (slot 260 = usum)
#define PICK_OFF 2356           // chosen example index [1]
#define K_OFF    2360
#define SMEM_FLOATS 58112       // 232448 B / 4
#define KCAP     (SMEM_FLOATS - K_OFF)
#define SMEM_BYTES (SMEM_FLOATS * 4)
#define UTOP_SLOT 259

// Deterministic 3-way product: bit-identical across all transport recomputes.
__device__ __forceinline__ float tmul3(float u, float k, float v) {
    return __fmul_rn(__fmul_rn(u, k), v);
}

__device__ __forceinline__ unsigned int smem_u32_of(const void* p) {
    unsigned int a;
    asm("{ .reg .u64 t; cvta.to.shared.u64 t, %1; cvt.u32.u64 %0, t; }" : "=r"(a) : "l"(p));
    return a;
}
__device__ __forceinline__ unsigned int mapa_u32(unsigned int laddr, unsigned int r) {
    unsigned int a;
    asm("mapa.shared::cluster.u32 %0, %1, %2;" : "=r"(a) : "r"(laddr), "r"(r));
    return a;
}
__device__ __forceinline__ void sts_remote_f32(unsigned int ra, float v) {
    asm volatile("st.shared::cluster.f32 [%0], %1;" :: "r"(ra), "f"(v) : "memory");
}
#define CLUSTER_SYNC_() do { \
    asm volatile("barrier.cluster.arrive.aligned;" ::: "memory"); \
    asm volatile("barrier.cluster.wait.aligned;" ::: "memory"); } while (0)

// COOP: this CTA owns rows [rbase, rbase+local_n) of an example split across a
// 2-CTA cluster. Solo (COOP=false): rbase=0, local_n=nt — exact R13 fp32 path.
template<bool COOP>
__device__ void run_ex(const float* __restrict__ aff, int nt, int nd,
                       int rbase, int local_n, int rank,
                       float* __restrict__ oT, float* __restrict__ oA,
                       float* sm)
{
    const int tid  = threadIdx.x;
    const int lane = tid & 31;
    const int w    = tid >> 5;

    // Row pitch: odd multiple of 4 -> conflict-free strided row loads.
    int ndp = (nd + 3) & ~3;
    if (((ndp >> 2) & 1) == 0) ndp += 4;
    const int ndh   = (ndp >> 1) & ~3;          // pass-1 col half boundary
    const int nth_l = (local_n >> 1) & ~3;      // pass-2 local row half boundary

    float* u_s    = sm + U_OFF;
    float* v_s    = sm + V_OFF;
    float* rmax_s = sm + RMAX_OFF;
    float* rhas   = sm + RHAS_OFF;
    float* cmax_s = sm + CMAX_OFF;
    float* sup    = sm + SUP_OFF;
    float* svp    = sm + SVP_OFF;
    float* scr    = sm + SCR_OFF;
    float* zrecv  = sm + SCR2_OFF;

    float* Kf     = sm + K_OFF;

    // Remote address of peer's zrecv (coop only)
    unsigned int peer_z = 0;
    if (COOP) peer_z = mapa_u32(smem_u32_of(zrecv), (unsigned int)(rank ^ 1));

    // Pass-1 identities: thread t and t+256 share local row (t&255), col halves.
    const int  row   = tid & 255;
    const bool up    = tid >= 256;
    const bool rowok = row < local_n;
    const int  p1beg = up ? ndh : 0;
    const int  p1end = up ? ndp : ndh;

    // Pass-2 identities: thread t and t+256 share col (t&255), local row halves.
    const int  col   = row;
    const bool colok = col < nd;
    const int  p2beg = up ? nth_l : 0;
    const int  p2end = up ? local_n : nth_l;

    // ---- Pre-zero K region (padding must be exactly 0) ----
    const int kwords = local_n * ndp;
    for (int i = tid * 4; i < kwords; i += NTHREADS * 4)
        *(float4*)(Kf + i) = make_float4(0.f, 0.f, 0.f, 0.f);

    // init v0 = 1 on c<=nd; interior partial sum = nd
    for (int c = tid; c < 260; c += NTHREADS) v_s[c] = (c <= nd) ? 1.f : 0.f;
    if (tid < 16) svp[tid] = (tid == 0) ? (float)nd : 0.f;
    __syncthreads();

    // ---- Build K = exp(10*aff) for LOCAL rows ----
    {
        const int cq0 = 4 * lane;
        const int cq1 = 4 * lane + 128;
        for (int r = w; r < local_n; r += 16) {
            const float* arow = aff + (size_t)(rbase + r) * 256;
            float* krow = Kf + (size_t)r * ndp;
            if (cq0 < nd) {
                float x[4];
                #pragma unroll
                for (int i = 0; i < 4; i++) { int c = cq0 + i; x[i] = (c < nd) ? __expf(10.0f * arow[c]) : 0.f; }
                *(float4*)(krow + cq0) = make_float4(x[0], x[1], x[2], x[3]);
            }
            if (cq1 < nd) {
                float x[4];
                #pragma unroll
                for (int i = 0; i < 4; i++) { int c = cq1 + i; x[i] = (c < nd) ? __expf(10.0f * arow[c]) : 0.f; }
                *(float4*)(krow + cq1) = make_float4(x[0], x[1], x[2], x[3]);
            }
        }
    }
    __syncthreads();

    const float ndf = (float)nd, ntf = (float)nt;
    const int   ndpS = ndp, ndp2 = 2 * ndp, ndp3 = 3 * ndp, ndp4s = 4 * ndp;

    // ================= up to 100 Sinkhorn iterations =================
    // Exact early exit on bitwise-stationary v (R13). In coop, both CTAs
    // compute bit-identical v => identical break iteration => sync-safe.
    for (int it = 0; it < 100; ++it) {
        // ---- Pass 1: u_r = 1/((Kv)_r + v[nd] + eps), local rows ----
        float sumv = v_s[nd];
        #pragma unroll
        for (int k = 0; k < 16; k++) sumv += svp[k];
        const float u_top = ndf / (sumv + EPS_C);
        const float v_dum = v_s[nd];

        float dot = 0.f;
        if (rowok) {
            float a0 = 0.f, a1 = 0.f, a2 = 0.f, a3 = 0.f;
            const float* krow = Kf + (size_t)row * ndp;
            #pragma unroll 4
            for (int c = p1beg; c < p1end; c += 4) {
                float4 kk = *(const float4*)(krow + c);
                float4 vv = *(const float4*)(v_s + c);         // warp-uniform broadcast
                a0 = fmaf(kk.x, vv.x, a0); a1 = fmaf(kk.y, vv.y, a1);
                a2 = fmaf(kk.z, vv.z, a2); a3 = fmaf(kk.w, vv.w, a3);
            }
            dot = (a0 + a1) + (a2 + a3);
        }
        if (up && rowok) scr[row] = dot;
        __syncthreads();                                       // B1

        float u_val = 0.f;
        if (!up && rowok) {
            float d = dot + scr[row];
            u_val = 1.0f / (d + v_dum + EPS_C);
            u_s[row] = u_val;
        }
        if (tid == 0) u_s[UTOP_SLOT] = u_top;
        float su = u_val;                                      // 0 for upper half
        #pragma unroll
        for (int o = 16; o > 0; o >>= 1) su += __shfl_xor_sync(0xffffffffu, su, o);
        if (lane == 0) sup[w] = su;
        __syncthreads();                                       // B2

        // local sum(u) over this CTA's rows
        float usum_loc = 0.f;
        #pragma unroll
        for (int k = 0; k < 16; k++) usum_loc += sup[k];

        // ---- Pass 2: z_c = (K^T u)_c over LOCAL rows ----
        float z = 0.f;
        if (colok) {
            float z0 = 0.f, z1 = 0.f, z2 = 0.f, z3 = 0.f;
            int r = p2beg;
            const float* p = Kf + col + (size_t)p2beg * ndp;
            for (; r + 3 < p2end; r += 4) {
                float4 uu = *(const float4*)(u_s + r);         // broadcast (r mult of 4)
                z0 = fmaf(p[0],     uu.x, z0);
                z1 = fmaf(p[ndpS],  uu.y, z1);
                z2 = fmaf(p[ndp2],  uu.z, z2);
                z3 = fmaf(p[ndp3],  uu.w, z3);
                p += ndp4s;
            }
            for (; r < p2end; r++) { z0 = fmaf(p[0], u_s[r], z0); p += ndpS; }
            z = (z0 + z1) + (z2 + z3);
        }
        if (up && colok) scr[col] = z;
        __syncthreads();                                       // B3

        int conv = 1;
        if (COOP) {
            // local combine, then exchange z-partials + usum with peer
            float z_loc = (!up && colok) ? (z + scr[col]) : 0.f;
            if (tid < 256) {
                sts_remote_f32(peer_z + 4u * (unsigned int)tid, z_loc);
                if (tid == 0) sts_remote_f32(peer_z + 4u * 260u, usum_loc);
            }
            CLUSTER_SYNC_();                                   // SYNC1: data visible

            float myv = 0.f;
            if (!up && colok) {
                float zp = zrecv[col];
                float zt = (rank == 0) ? (z_loc + zp) : (zp + z_loc);  // rank-independent order
                myv = 1.0f / ((zt + u_top) + EPS_C);
                conv = (__float_as_uint(myv) == __float_as_uint(v_s[col]));
                v_s[col] = myv;
            }
            if (tid == 0) {
                float usum_p = zrecv[260];
                float st = (rank == 0) ? (usum_loc + usum_p) : (usum_p + usum_loc);
                float v_dnew = ntf / ((u_top + st) + EPS_C);
                conv &= (__float_as_uint(v_dnew) == __float_as_uint(v_dum));
                v_s[nd] = v_dnew;
            }
            float sv = myv;
            #pragma unroll
            for (int o = 16; o > 0; o >>= 1) sv += __shfl_xor_sync(0xffffffffu, sv, o);
            if (lane == 0) svp[w] = sv;
            int brk = __syncthreads_and(conv);                 // local vote (identical both CTAs)
            CLUSTER_SYNC_();                                   // SYNC2: buffer reusable
            if (brk) break;
        } else {
            // solo: exact R13 arithmetic
            const float sumu = u_top + usum_loc;
            const float v_dnew = ntf / (sumu + EPS_C);
            float myv = 0.f;
            if (!up && colok) {
                float zz = (z + scr[col]) + u_top;
                myv = 1.0f / (zz + EPS_C);
                conv = (__float_as_uint(myv) == __float_as_uint(v_s[col]));
                v_s[col] = myv;
            }
            if (tid == 0) {
                conv &= (__float_as_uint(v_dnew) == __float_as_uint(v_dum));
                v_s[nd] = v_dnew;
            }
            float sv = myv;
            #pragma unroll
            for (int o = 16; o > 0; o >>= 1) sv += __shfl_xor_sync(0xffffffffu, sv, o);
            if (lane == 0) svp[w] = sv;
            if (__syncthreads_and(conv)) break;                // B4 + exact exit
        }
    }

    // ================= Epilogue =================
    const float v_dF = v_s[nd];
    const float u_tF = u_s[UTOP_SLOT];
    const int   nd1  = nd + 1;

    if (tid < 260) rhas[tid] = 0.f;

    // E1: row max over LOCAL rows (half-split cols)
    float rmx = 0.f;
    if (rowok) {
        const float u = u_s[row];
        const float* krow = Kf + (size_t)row * ndp;
        #pragma unroll 4
        for (int c = p1beg; c < p1end; c += 4) {
            float4 kk = *(const float4*)(krow + c);
            float4 vv = *(const float4*)(v_s + c);
            rmx = fmaxf(rmx, tmul3(u, kk.x, vv.x));
            rmx = fmaxf(rmx, tmul3(u, kk.y, vv.y));
            rmx = fmaxf(rmx, tmul3(u, kk.z, vv.z));
            rmx = fmaxf(rmx, tmul3(u, kk.w, vv.w));
        }
    }
    if (up && rowok) scr[row] = rmx;
    __syncthreads();
    if (!up && rowok) rmax_s[row] = fmaxf(rmx, scr[row]);
    __syncthreads();

    // E2a: col max over LOCAL rows
    float cmx = 0.f;
    if (colok) {
        const float vc = v_s[col];
        const float* p = Kf + col + (size_t)p2beg * ndp;
        for (int r = p2beg; r < p2end; r++) { cmx = fmaxf(cmx, tmul3(u_s[r], p[0], vc)); p += ndpS; }
    }
    if (up && colok) scr[col] = cmx;
    __syncthreads();
    float cmax_loc = 0.f;
    if (!up && colok) cmax_loc = fmaxf(cmx, scr[col]);
    if (COOP) {
        if (tid < 256) sts_remote_f32(peer_z + 4u * (unsigned int)tid, cmax_loc);
        CLUSTER_SYNC_();
        if (!up && colok) cmax_s[col] = fmaxf(cmax_loc, zrecv[col]);
    } else {
        if (!up && colok) cmax_s[col] = cmax_loc;
    }
    __syncthreads();

    // E2b: writes over LOCAL rows; colhas accumulation per column
    float colhas = 0.f;
    if (colok) {
        const float vc = v_s[col];
        const float cf = cmax_s[col];
        const float* p = Kf + col + (size_t)p2beg * ndp;
        for (int r = p2beg; r < p2end; r++) {
            float t = tmul3(u_s[r], p[0], vc);
            bool  a = (t == rmax_s[r]) && (t == cf);
            size_t idx = (size_t)(rbase + r) * nd1 + col;
            oT[idx] = t; oA[idx] = a ? 1.f : 0.f;
            if (a) { colhas = 1.f; rhas[r] = 1.f; }            // benign same-value races
            p += ndpS;
        }
    }
    if (up && colok) scr[col] = colhas;
    __syncthreads();
    float colhas_loc = 0.f;
    if (!up && colok) colhas_loc = fmaxf(colhas, scr[col]);
    if (COOP) {
        if (tid < 256) sts_remote_f32(peer_z + 4u * (unsigned int)tid, colhas_loc);
        CLUSTER_SYNC_();
        if (rank == 0 && !up && colok) {                       // births row (rank0 only)
            float tot = fmaxf(colhas_loc, zrecv[col]);
            size_t bidx = (size_t)nt * nd1 + col;
            oT[bidx] = __fmul_rn(u_tF, v_s[col]);
            oA[bidx] = (tot > 0.f) ? 0.f : 1.f;
        }
    } else {
        if (!up && colok) {
            size_t bidx = (size_t)nt * nd1 + col;
            oT[bidx] = __fmul_rn(u_tF, v_s[col]);
            oA[bidx] = (colhas_loc > 0.f) ? 0.f : 1.f;
        }
    }
    __syncthreads();

    if (tid < local_n) {                                       // deaths column (local rows)
        size_t idx = (size_t)(rbase + tid) * nd1 + nd;
        oT[idx] = __fmul_rn(u_s[tid], v_dF);
        oA[idx] = (rhas[tid] > 0.f) ? 0.f : 1.f;
    }
    if ((!COOP || rank == 0) && tid == 0) {                    // corner
        size_t idx = (size_t)nt * nd1 + nd;
        oT[idx] = __fmul_rn(u_tF, v_dF);
        oA[idx] = 0.f;
    }
    // zero pad tail (split across the pair in coop)
    const int length = (nt + 1) * nd1;
    const int start  = length + (COOP ? rank * NTHREADS : 0) + tid;
    const int step   = COOP ? 2 * NTHREADS : NTHREADS;
    for (int k = start; k < L_PAD; k += step) { oT[k] = 0.f; oA[k] = 0.f; }
}

__global__ void __launch_bounds__(NTHREADS, 1)
assoc_kernel(const float* __restrict__ aff, const int* __restrict__ ndet,
             const int* __restrict__ ntrk, float* __restrict__ outT,
             float* __restrict__ outA, int Bn)
{
    extern __shared__ float sm[];
    const int tid   = threadIdx.x;
    const int cid   = blockIdx.x >> 1;      // cluster id (cluster dims (2,1,1))
    const int crank = blockIdx.x & 1;       // rank within cluster

    // ---- LPT remap + coop/solo split ----
    int* cost_s = (int*)(sm + RMAX_OFF);    // [Bn]
    int* pick_s = (int*)(sm + PICK_OFF);    // [1]
    if (tid < Bn) cost_s[tid] = (ntrk[tid] + 1) * (ndet[tid] + 1);
    __syncthreads();
    int nb = 0, myrank = 0;
    {
        const int myc = (tid < Bn) ? cost_s[tid] : -1;
        for (int j = 0; j < Bn; j++) {
            int cj = cost_s[j];
            nb += (cj > CUT_COST);
            myrank += (cj > myc) || (cj == myc && j < tid);
        }
    }
    const bool coop = (cid < nb);
    const int target = coop ? cid : (nb + 2 * (cid - nb) + crank);

    bool active = (target < Bn);
    int b = 0;
    if (active) {
        if (tid < Bn && myrank == target) *pick_s = tid;
        __syncthreads();
        b = *pick_s;
        __syncthreads();                    // everyone read b before sm reuse
    }

    if (active) {
        const int nd = ndet[b];
        const int nt = ntrk[b];
        const float* affb = aff + (size_t)b * (256 * 256);
        float* oT = outT + (size_t)b * L_PAD;
        float* oA = outA + (size_t)b * L_PAD;

        if (coop) {
            const int half = (nt >> 1) & ~3;
            const int rbase   = crank ? half : 0;
            const int local_n = crank ? (nt - half) : half;
            run_ex<true >(affb, nt, nd, rbase, local_n, crank, oT, oA, sm);
        } else {
            run_ex<false>(affb, nt, nd, 0, nt, 0, oT, oA, sm);
        }
    }
}

extern "C" void kernel_launch(void* const* d_in, const int* in_sizes, int n_in,
                              void* d_out, int out_size)
{
    const float* aff  = (const float*)d_in[0];
    const int*   ndet = (const int*)d_in[1];
    const int*   ntrk = (const int*)d_in[2];
    const int    Bn   = in_sizes[1];

    float* out  = (float*)d_out;
    float* outA = out + (size_t)(out_size / 2);   // [t_flat | a_flat]

    cudaFuncSetAttribute(assoc_kernel, cudaFuncAttributeMaxDynamicSharedMemorySize, SMEM_BYTES);

    cudaLaunchConfig_t cfg = {};
    cfg.gridDim  = dim3((unsigned)(2 * Bn), 1, 1);
    cfg.blockDim = dim3(NTHREADS, 1, 1);
    cfg.dynamicSmemBytes = SMEM_BYTES;
    cfg.stream = 0;
    cudaLaunchAttribute attrs[1];
    attrs[0].id = cudaLaunchAttributeClusterDimension;
    attrs[0].val.clusterDim.x = 2;
    attrs[0].val.clusterDim.y = 1;
    attrs[0].val.clusterDim.z = 1;
    cfg.attrs = attrs;
    cfg.numAttrs = 1;
    cudaLaunchKernelEx(&cfg, assoc_kernel, aff, ndet, ntrk, out, outA, Bn);
}

// round 17
// speedup vs baseline: 1.0626x; 1.0626x over previous
#include <cuda_runtime.h>
#include <cuda_fp16.h>

// B=256, T_MAX=D_MAX=256, TP=DP=257
#define NTHREADS 512
#define L_PAD    66049          // 257*257
#define EPS_C    1e-12f

// Shared layout (floats)
#define U_OFF    0              // u[260]
#define V_OFF    260            // v[260]
#define RMAX_OFF 520            // row max [260]     (reused as cost[] during remap)
#define RHAS_OFF 780            // row-has-assignment flags [260]
#define CMAX_OFF 1040           // col max [260]
#define SUP_OFF  1300           // per-warp sum(u) partials [16]
#define SVP_OFF  1316           // per-warp sum(v) partials [16]
#define SCR_OFF  1332           // half-split combine scratch [256]
#define SCR2_OFF 1588           // fp16 quarter-combine scratch [768] (3 x 256)
#define PICK_OFF 2356           // chosen example index [1]
#define K_OFF    2360
#define SMEM_FLOATS 58112       // 232448 B / 4
#define KCAP     (SMEM_FLOATS - K_OFF)   // 55752 fp32 slots
#define SMEM_BYTES (SMEM_FLOATS * 4)

// Deterministic 3-way product: bit-identical across all transport recomputes.
__device__ __forceinline__ float tmul3(float u, float k, float v) {
    return __fmul_rn(__fmul_rn(u, k), v);
}

template<bool F32>
__device__ void run_ex(const float* __restrict__ aff, int nt, int nd,
                       float* __restrict__ oT, float* __restrict__ oA,
                       float* sm)
{
    const int tid  = threadIdx.x;
    const int lane = tid & 31;
    const int w    = tid >> 5;

    // Row pitch: odd multiple of 4 (fp32) / 8 (fp16) -> conflict-free
    // strided row loads in pass 1 (8-lane wavefront quads form a bijection).
    int ndp;
    if (F32) { ndp = (nd + 3) & ~3; if (((ndp >> 2) & 1) == 0) ndp += 4; }
    else     { ndp = (nd + 7) & ~7; if (((ndp >> 3) & 1) == 0) ndp += 8; }

    // Contiguous half-split boundaries for pass 1 (vector-aligned).
    const int ndh = F32 ? ((ndp >> 1) & ~3) : ((ndp >> 1) & ~7);
    const int nth = (nt >> 1) & ~3;

    float*  u_s    = sm + U_OFF;
    float*  v_s    = sm + V_OFF;
    float*  rmax_s = sm + RMAX_OFF;
    float*  rhas   = sm + RHAS_OFF;
    float*  cmax_s = sm + CMAX_OFF;
    float*  sup    = sm + SUP_OFF;
    float*  svp    = sm + SVP_OFF;
    float*  scr    = sm + SCR_OFF;
    float*  scr2   = sm + SCR2_OFF;
    float*  Kf     = sm + K_OFF;
    __half* Kh     = (__half*)(sm + K_OFF);

    // Pass-1 identities: thread t and t+256 share row (t&255), each takes a half.
    const int  row   = tid & 255;
    const bool up    = tid >= 256;
    const bool rowok = row < nt;
    const int  p1beg = up ? ndh : 0;
    const int  p1end = up ? ndp : ndh;

    // fp32 pass-2 identities (half rows per column; proven R8)
    const int  col   = row;
    const bool colok = col < nd;
    const int  p2beg = up ? nth : 0;
    const int  p2end = up ? nt  : nth;

    // fp16 pass-2 identities: column pair (2cp, 2cp+1) x row quarter qq (proven R9)
    const int cp   = tid & 127;
    const int qq   = tid >> 7;
    const int c0   = 2 * cp, c1 = 2 * cp + 1;
    const int qb1  = (nt >> 2) & ~3;
    const int qb2  = (nt >> 1) & ~3;
    const int qb3  = ((3 * nt) >> 2) & ~3;
    const int rqb  = (qq == 0) ? 0   : (qq == 1) ? qb1 : (qq == 2) ? qb2 : qb3;
    const int rqe  = (qq == 0) ? qb1 : (qq == 1) ? qb2 : (qq == 2) ? qb3 : nt;
    const int ndp_h2 = ndp >> 1;

    // ---- Pre-zero K region (padding must be exactly 0) ----
    const int kwords = F32 ? nt * ndp : (nt * ndp) >> 1;   // floats, mult of 4
    for (int i = tid * 4; i < kwords; i += NTHREADS * 4)
        *(float4*)(Kf + i) = make_float4(0.f, 0.f, 0.f, 0.f);

    // init v0 = 1 on c<=nd; interior partial sum = nd
    for (int c = tid; c < 260; c += NTHREADS) v_s[c] = (c <= nd) ? 1.f : 0.f;
    if (tid < 16) svp[tid] = (tid == 0) ? (float)nd : 0.f;
    __syncthreads();

    // ---- Build K = exp(10*aff) on interior ----
    {
        const int cq0 = F32 ? 4 * lane : 8 * lane;
        const int cq1 = 4 * lane + 128;
        for (int r = w; r < nt; r += 16) {
            const float* arow = aff + (size_t)r * 256;
            if (F32) {
                float* krow = Kf + (size_t)r * ndp;
                if (cq0 < nd) {
                    float x[4];
                    #pragma unroll
                    for (int i = 0; i < 4; i++) { int c = cq0 + i; x[i] = (c < nd) ? __expf(10.0f * arow[c]) : 0.f; }
                    *(float4*)(krow + cq0) = make_float4(x[0], x[1], x[2], x[3]);
                }
                if (cq1 < nd) {
                    float x[4];
                    #pragma unroll
                    for (int i = 0; i < 4; i++) { int c = cq1 + i; x[i] = (c < nd) ? __expf(10.0f * arow[c]) : 0.f; }
                    *(float4*)(krow + cq1) = make_float4(x[0], x[1], x[2], x[3]);
                }
            } else {
                __half* krow = Kh + (size_t)r * ndp;
                if (cq0 < nd) {
                    __half h[8];
                    #pragma unroll
                    for (int i = 0; i < 8; i++) { int c = cq0 + i; h[i] = __float2half_rn((c < nd) ? __expf(10.0f * arow[c]) : 0.f); }
                    *(uint4*)(krow + cq0) = *(uint4*)h;
                }
            }
        }
    }
    __syncthreads();

    const float ndf = (float)nd, ntf = (float)nt;
    const int   ndpS = ndp, ndp2 = 2 * ndp, ndp3 = 3 * ndp, ndp4 = 4 * ndp;
    const int   ndp5 = 5 * ndp, ndp6 = 6 * ndp, ndp7 = 7 * ndp, ndp8 = 8 * ndp;

    // ================= up to 100 Sinkhorn iterations =================
    // Exact early exit when v is bitwise stationary across one iteration.
    for (int it = 0; it < 100; ++it) {
        // ---- Pass 1: u_r = 1/((Kv)_r + v[nd] + eps), half-split ----
        float sumv = v_s[nd];
        #pragma unroll
        for (int k = 0; k < 16; k++) sumv += svp[k];
        const float u_top = ndf / (sumv + EPS_C);
        const float v_dum = v_s[nd];

        float dot = 0.f;
        if (rowok) {
            float a0 = 0.f, a1 = 0.f, a2 = 0.f, a3 = 0.f;
            if (F32) {
                const float* krow = Kf + (size_t)row * ndp;
                #pragma unroll 8
                for (int c = p1beg; c < p1end; c += 4) {
                    float4 kk = *(const float4*)(krow + c);
                    float4 vv = *(const float4*)(v_s + c);     // warp-uniform broadcast
                    a0 = fmaf(kk.x, vv.x, a0); a1 = fmaf(kk.y, vv.y, a1);
                    a2 = fmaf(kk.z, vv.z, a2); a3 = fmaf(kk.w, vv.w, a3);
                }
            } else {
                const __half* krow = Kh + (size_t)row * ndp;
                #pragma unroll 2
                for (int c = p1beg; c < p1end; c += 8) {
                    uint4  raw = *(const uint4*)(krow + c);
                    float4 v0  = *(const float4*)(v_s + c);
                    float4 v1  = *(const float4*)(v_s + c + 4);
                    float2 f;
                    f = __half22float2(*(__half2*)&raw.x); a0 = fmaf(f.x, v0.x, a0); a1 = fmaf(f.y, v0.y, a1);
                    f = __half22float2(*(__half2*)&raw.y); a2 = fmaf(f.x, v0.z, a2); a3 = fmaf(f.y, v0.w, a3);
                    f = __half22float2(*(__half2*)&raw.z); a0 = fmaf(f.x, v1.x, a0); a1 = fmaf(f.y, v1.y, a1);
                    f = __half22float2(*(__half2*)&raw.w); a2 = fmaf(f.x, v1.z, a2); a3 = fmaf(f.y, v1.w, a3);
                }
            }
            dot = (a0 + a1) + (a2 + a3);
        }
        if (up && rowok) scr[row] = dot;
        __syncthreads();                                   // B1

        float u_val = 0.f;
        if (!up && rowok) {
            float d = dot + scr[row];
            u_val = 1.0f / (d + v_dum + EPS_C);
            u_s[row] = u_val;
        }
        if (tid == 0) u_s[nt] = u_top;
        float su = u_val;                                  // 0 for upper half
        #pragma unroll
        for (int o = 16; o > 0; o >>= 1) su += __shfl_xor_sync(0xffffffffu, su, o);
        if (lane == 0) sup[w] = su;
        __syncthreads();                                   // B2

        // ---- Pass 2: v_c = 1/((K^T u)_c + u_top + eps) ----
        float sumu = u_top;
        #pragma unroll
        for (int k = 0; k < 16; k++) sumu += sup[k];
        const float v_dnew = ntf / (sumu + EPS_C);

        int conv = 1;                                      // per-thread stationarity vote
        if (F32) {
            float z = 0.f;
            if (colok) {
                float z0 = 0.f, z1 = 0.f, z2 = 0.f, z3 = 0.f;
                float z4 = 0.f, z5 = 0.f, z6 = 0.f, z7 = 0.f;
                int r = p2beg;
                const float* p = Kf + col + (size_t)p2beg * ndp;
                for (; r + 7 < p2end; r += 8) {            // 8 independent LDS in flight
                    float4 ua = *(const float4*)(u_s + r);
                    float4 ub = *(const float4*)(u_s + r + 4);
                    z0 = fmaf(p[0],     ua.x, z0);
                    z1 = fmaf(p[ndpS],  ua.y, z1);
                    z2 = fmaf(p[ndp2],  ua.z, z2);
                    z3 = fmaf(p[ndp3],  ua.w, z3);
                    z4 = fmaf(p[ndp4],  ub.x, z4);
                    z5 = fmaf(p[ndp5],  ub.y, z5);
                    z6 = fmaf(p[ndp6],  ub.z, z6);
                    z7 = fmaf(p[ndp7],  ub.w, z7);
                    p += ndp8;
                }
                for (; r + 3 < p2end; r += 4) {
                    float4 uu = *(const float4*)(u_s + r);
                    z0 = fmaf(p[0],     uu.x, z0);
                    z1 = fmaf(p[ndpS],  uu.y, z1);
                    z2 = fmaf(p[ndp2],  uu.z, z2);
                    z3 = fmaf(p[ndp3],  uu.w, z3);
                    p += ndp4;
                }
                for (; r < p2end; r++) { z0 = fmaf(p[0], u_s[r], z0); p += ndpS; }
                z = ((z0 + z4) + (z1 + z5)) + ((z2 + z6) + (z3 + z7));
            }
            if (up && colok) scr[col] = z;
            __syncthreads();                               // B3

            float myv = 0.f;
            if (!up && colok) {
                float zz = (z + scr[col]) + u_top;
                myv = 1.0f / (zz + EPS_C);
                conv = (__float_as_uint(myv) == __float_as_uint(v_s[col]));
                v_s[col] = myv;
            }
            if (tid == 0) {
                conv &= (__float_as_uint(v_dnew) == __float_as_uint(v_dum));
                v_s[nd] = v_dnew;
            }
            float sv = myv;
            #pragma unroll
            for (int o = 16; o > 0; o >>= 1) sv += __shfl_xor_sync(0xffffffffu, sv, o);
            if (lane == 0) svp[w] = sv;
            if (__syncthreads_and(conv)) break;            // B4 + exact early exit
        } else {
            // fp16: col-pair half2 loads, 4-way row quarters (proven R9).
            float zxa = 0.f, zya = 0.f, zxb = 0.f, zyb = 0.f;
            {
                const __half2* p = (const __half2*)Kh + (size_t)rqb * ndp_h2 + cp;
                int r = rqb;
                for (; r + 3 < rqe; r += 4) {
                    float4 uu = *(const float4*)(u_s + r);     // broadcast (rqb mult of 4)
                    float2 k0 = __half22float2(p[0]);
                    float2 k1 = __half22float2(p[ndp_h2]);
                    float2 k2 = __half22float2(p[2 * ndp_h2]);
                    float2 k3 = __half22float2(p[3 * ndp_h2]);
                    zxa = fmaf(k0.x, uu.x, zxa); zya = fmaf(k0.y, uu.x, zya);
                    zxb = fmaf(k1.x, uu.y, zxb); zyb = fmaf(k1.y, uu.y, zyb);
                    zxa = fmaf(k2.x, uu.z, zxa); zya = fmaf(k2.y, uu.z, zya);
                    zxb = fmaf(k3.x, uu.w, zxb); zyb = fmaf(k3.y, uu.w, zyb);
                    p += 4 * ndp_h2;
                }
                for (; r < rqe; r++) {
                    float2 kk = __half22float2(p[0]);
                    float  ur = u_s[r];
                    zxa = fmaf(kk.x, ur, zxa); zya = fmaf(kk.y, ur, zya);
                    p += ndp_h2;
                }
            }
            float zx = zxa + zxb, zy = zya + zyb;
            if (qq > 0) *(float2*)(scr2 + (size_t)(qq - 1) * 256 + 2 * cp) = make_float2(zx, zy);
            __syncthreads();                               // B3

            float svq = 0.f;
            if (qq == 0) {
                #pragma unroll
                for (int k = 0; k < 3; k++) {
                    float2 o = *(float2*)(scr2 + (size_t)k * 256 + 2 * cp);
                    zx += o.x; zy += o.y;
                }
                if (c0 < nd) {
                    float v0 = 1.0f / ((zx + u_top) + EPS_C);
                    conv &= (__float_as_uint(v0) == __float_as_uint(v_s[c0]));
                    v_s[c0] = v0; svq += v0;
                }
                if (c1 < nd) {
                    float v1 = 1.0f / ((zy + u_top) + EPS_C);
                    conv &= (__float_as_uint(v1) == __float_as_uint(v_s[c1]));
                    v_s[c1] = v1; svq += v1;
                }
            }
            if (tid == 0) {
                conv &= (__float_as_uint(v_dnew) == __float_as_uint(v_dum));
                v_s[nd] = v_dnew;
            }
            #pragma unroll
            for (int o = 16; o > 0; o >>= 1) svq += __shfl_xor_sync(0xffffffffu, svq, o);
            if (lane == 0) svp[w] = svq;
            if (__syncthreads_and(conv)) break;            // B4 + exact early exit
        }
    }

    // ================= Epilogue =================
    const float v_dF = v_s[nd];
    const float u_tF = u_s[nt];
    const int   nd1  = nd + 1;

    if (tid < 260) rhas[tid] = 0.f;

    // E1: row max (half-split per row)
    float rmx = 0.f;
    if (rowok) {
        const float u = u_s[row];
        if (F32) {
            const float* krow = Kf + (size_t)row * ndp;
            #pragma unroll 4
            for (int c = p1beg; c < p1end; c += 4) {
                float4 kk = *(const float4*)(krow + c);
                float4 vv = *(const float4*)(v_s + c);
                rmx = fmaxf(rmx, tmul3(u, kk.x, vv.x));
                rmx = fmaxf(rmx, tmul3(u, kk.y, vv.y));
                rmx = fmaxf(rmx, tmul3(u, kk.z, vv.z));
                rmx = fmaxf(rmx, tmul3(u, kk.w, vv.w));
            }
        } else {
            const __half* krow = Kh + (size_t)row * ndp;
            for (int c = p1beg; c < p1end; c++)
                rmx = fmaxf(rmx, tmul3(u, __half2float(krow[c]), v_s[c]));
        }
    }
    if (up && rowok) scr[row] = rmx;
    __syncthreads();
    if (!up && rowok) rmax_s[row] = fmaxf(rmx, scr[row]);
    __syncthreads();

    if (F32) {
        // ---- fp32 epilogue column passes (proven R8, E2a with 2 accumulators) ----
        float cmx = 0.f;
        if (colok) {
            const float vc = v_s[col];
            float m0 = 0.f, m1 = 0.f;
            int r = p2beg;
            const float* p = Kf + col + (size_t)p2beg * ndp;
            for (; r + 1 < p2end; r += 2) {
                m0 = fmaxf(m0, tmul3(u_s[r],     p[0],    vc));
                m1 = fmaxf(m1, tmul3(u_s[r + 1], p[ndpS], vc));
                p += ndp2;
            }
            for (; r < p2end; r++) { m0 = fmaxf(m0, tmul3(u_s[r], p[0], vc)); p += ndpS; }
            cmx = fmaxf(m0, m1);
        }
        if (up && colok) scr[col] = cmx;
        __syncthreads();
        if (!up && colok) cmax_s[col] = fmaxf(cmx, scr[col]);
        __syncthreads();

        float colhas = 0.f;
        if (colok) {
            const float vc = v_s[col];
            const float cf = cmax_s[col];
            const float* p = Kf + col + (size_t)p2beg * ndp;
            for (int r = p2beg; r < p2end; r++) {
                float t = tmul3(u_s[r], p[0], vc);
                bool  a = (t == rmax_s[r]) && (t == cf);
                size_t idx = (size_t)r * nd1 + col;
                oT[idx] = t; oA[idx] = a ? 1.f : 0.f;
                if (a) { colhas = 1.f; rhas[r] = 1.f; }    // benign same-value races
                p += ndpS;
            }
        }
        if (up && colok) scr[col] = colhas;
        __syncthreads();
        if (!up && colok) {                                // births row
            colhas = fmaxf(colhas, scr[col]);
            size_t bidx = (size_t)nt * nd1 + col;
            oT[bidx] = __fmul_rn(u_tF, v_s[col]);
            oA[bidx] = (colhas > 0.f) ? 0.f : 1.f;
        }
        __syncthreads();
    } else {
        // ---- fp16 epilogue: col-pair x quarter layout (proven R9) ----
        const float vc0 = (c0 < nd) ? v_s[c0] : 0.f;
        const float vc1 = (c1 < nd) ? v_s[c1] : 0.f;

        // E2a: col max
        float cmx0 = 0.f, cmx1 = 0.f;
        {
            const __half2* p = (const __half2*)Kh + (size_t)rqb * ndp_h2 + cp;
            for (int r = rqb; r < rqe; r++) {
                float2 kk = __half22float2(p[0]);
                cmx0 = fmaxf(cmx0, tmul3(u_s[r], kk.x, vc0));
                cmx1 = fmaxf(cmx1, tmul3(u_s[r], kk.y, vc1));
                p += ndp_h2;
            }
        }
        if (qq > 0) *(float2*)(scr2 + (size_t)(qq - 1) * 256 + 2 * cp) = make_float2(cmx0, cmx1);
        __syncthreads();
        if (qq == 0) {
            #pragma unroll
            for (int k = 0; k < 3; k++) {
                float2 o = *(float2*)(scr2 + (size_t)k * 256 + 2 * cp);
                cmx0 = fmaxf(cmx0, o.x); cmx1 = fmaxf(cmx1, o.y);
            }
            if (c0 < nd) cmax_s[c0] = cmx0;
            if (c1 < nd) cmax_s[c1] = cmx1;
        }
        __syncthreads();

        // E2b: write pass over quarter's rows for both cols
        const float cf0 = (c0 < nd) ? cmax_s[c0] : 0.f;
        const float cf1 = (c1 < nd) ? cmax_s[c1] : 0.f;
        float ch0 = 0.f, ch1 = 0.f;
        {
            const __half2* p = (const __half2*)Kh + (size_t)rqb * ndp_h2 + cp;
            for (int r = rqb; r < rqe; r++) {
                float2 kk = __half22float2(p[0]);
                float  rf = rmax_s[r];
                size_t rb = (size_t)r * nd1;
                if (c0 < nd) {
                    float t = tmul3(u_s[r], kk.x, vc0);
                    bool  a = (t == rf) && (t == cf0);
                    oT[rb + c0] = t; oA[rb + c0] = a ? 1.f : 0.f;
                    if (a) { ch0 = 1.f; rhas[r] = 1.f; }
                }
                if (c1 < nd) {
                    float t = tmul3(u_s[r], kk.y, vc1);
                    bool  a = (t == rf) && (t == cf1);
                    oT[rb + c1] = t; oA[rb + c1] = a ? 1.f : 0.f;
                    if (a) { ch1 = 1.f; rhas[r] = 1.f; }
                }
                p += ndp_h2;
            }
        }
        if (qq > 0) *(float2*)(scr2 + (size_t)(qq - 1) * 256 + 2 * cp) = make_float2(ch0, ch1);
        __syncthreads();
        if (qq == 0) {
            #pragma unroll
            for (int k = 0; k < 3; k++) {
                float2 o = *(float2*)(scr2 + (size_t)k * 256 + 2 * cp);
                ch0 = fmaxf(ch0, o.x); ch1 = fmaxf(ch1, o.y);
            }
            size_t bb = (size_t)nt * nd1;                  // births row
            if (c0 < nd) { oT[bb + c0] = __fmul_rn(u_tF, vc0); oA[bb + c0] = (ch0 > 0.f) ? 0.f : 1.f; }
            if (c1 < nd) { oT[bb + c1] = __fmul_rn(u_tF, vc1); oA[bb + c1] = (ch1 > 0.f) ? 0.f : 1.f; }
        }
        __syncthreads();
    }

    if (tid < nt) {                                      // deaths column
        size_t idx = (size_t)tid * nd1 + nd;
        oT[idx] = __fmul_rn(u_s[tid], v_dF);
        oA[idx] = (rhas[tid] > 0.f) ? 0.f : 1.f;
    }
    if (tid == 0) {                                      // corner
        size_t idx = (size_t)nt * nd1 + nd;
        oT[idx] = __fmul_rn(u_tF, v_dF);
        oA[idx] = 0.f;
    }
    const int length = (nt + 1) * nd1;                   // zero pad tail
    for (int k = length + tid; k < L_PAD; k += NTHREADS) { oT[k] = 0.f; oA[k] = 0.f; }
}

__global__ void __launch_bounds__(NTHREADS, 1)
assoc_kernel(const float* __restrict__ aff, const int* __restrict__ ndet,
             const int* __restrict__ ntrk, float* __restrict__ outT,
             float* __restrict__ outA, int Bn)
{
    extern __shared__ float sm[];
    const int tid = threadIdx.x;

    // ---- LPT remap: block bid handles the example with cost-rank bid ----
    int* cost_s = (int*)(sm + RMAX_OFF);    // [Bn] (Bn <= 512)
    int* pick_s = (int*)(sm + PICK_OFF);    // [1]
    if (tid < Bn) cost_s[tid] = (ntrk[tid] + 1) * (ndet[tid] + 1);
    __syncthreads();
    if (tid < Bn) {
        const int myc = cost_s[tid];
        int rank = 0;
        for (int j = 0; j < Bn; j++) {
            int cj = cost_s[j];
            rank += (cj > myc) || (cj == myc && j < tid);
        }
        if (rank == (int)blockIdx.x) *pick_s = tid;
    }
    __syncthreads();
    const int b = *pick_s;
    __syncthreads();   // everyone has read b before sm is reused

    const int nd = ndet[b];
    const int nt = ntrk[b];
    const float* affb = aff + (size_t)b * (256 * 256);
    float* oT = outT + (size_t)b * L_PAD;
    float* oA = outA + (size_t)b * L_PAD;

    int ndp4 = (nd + 3) & ~3;
    if (((ndp4 >> 2) & 1) == 0) ndp4 += 4;
    if (nt * ndp4 <= KCAP) run_ex<true >(affb, nt, nd, oT, oA, sm);
    else                   run_ex<false>(affb, nt, nd, oT, oA, sm);
}

extern "C" void kernel_launch(void* const* d_in, const int* in_sizes, int n_in,
                              void* d_out, int out_size)
{
    const float* aff  = (const float*)d_in[0];
    const int*   ndet = (const int*)d_in[1];
    const int*   ntrk = (const int*)d_in[2];
    const int    Bn   = in_sizes[1];

    float* out  = (float*)d_out;
    float* outA = out + (size_t)(out_size / 2);   // [t_flat | a_flat]

    cudaFuncSetAttribute(assoc_kernel, cudaFuncAttributeMaxDynamicSharedMemorySize, SMEM_BYTES);
    assoc_kernel<<<Bn, NTHREADS, SMEM_BYTES>>>(aff, ndet, ntrk, out, outA, Bn);
}